// round 16
// baseline (speedup 1.0000x reference)
#include <cuda_runtime.h>
#include <cuda_bf16.h>
#include <cstddef>

// ---------------- problem dims ----------------
#define BB 16
#define SS 96
#define KK 10
#define FF 256
#define NS 1536            // BB*SS samples
#define CIN 3
#define HW 64
#define FEATC 30752        // 32*31*31
#define KDIM 30752

#define TAUc 0.05f
#define RHOc 10.0f
#define LRc 0.5f
#define NSTEPS 60

// GEMM tiling
#define BM 128
#define BN 64
#define BKT 32
#define STAGES 3
#define LDA 40              // halves per smem row (stride-40 => conflict-free 4B LDS)
#define SPLITK 4

// weight-transpose tail blocks: 256 n * 16 pixel-chunks
#define WT_BLOCKS (FF * 16)

// ---------------- scratch (__device__ globals; no allocations) ----------------
// Feature k-index permuted: k' = pixel*32 + ch  (both F0 and W use it consistently)
__device__ __nv_bfloat16 g_F0h[(size_t)NS * KDIM];   // conv features hi
__device__ __nv_bfloat16 g_F0l[(size_t)NS * KDIM];   // conv features lo
__device__ __nv_bfloat16 g_Wh[(size_t)FF * KDIM];    // fc weights hi (permuted)
__device__ __nv_bfloat16 g_Wl[(size_t)FF * KDIM];    // fc weights lo (permuted)
__device__ float g_Cpart[SPLITK * NS * FF];          // split-K partials
__device__ float g_feats[NS * FF];                   // fc output features
__device__ float g_G[BB * SS * SS];                  // Gram
__device__ float g_D[BB * SS * SS];                  // pairwise sq distances
__device__ float g_pex[2][BB * KK * SS];             // ping-pong p exchange
__device__ unsigned g_bar_count;
__device__ unsigned g_bar_gen;

// ---------------- helpers ----------------
__device__ __forceinline__ void bf16split(float v, __nv_bfloat16& h, __nv_bfloat16& l) {
    h = __float2bfloat16(v);
    l = __float2bfloat16(v - __bfloat162float(h));
}

__device__ __forceinline__ unsigned long long pk2(float lo, float hi) {
    unsigned long long r;
    asm("mov.b64 %0, {%1,%2};" : "=l"(r) : "f"(lo), "f"(hi));
    return r;
}
__device__ __forceinline__ float2 upk2(unsigned long long v) {
    float2 f;
    asm("mov.b64 {%0,%1}, %2;" : "=f"(f.x), "=f"(f.y) : "l"(v));
    return f;
}
__device__ __forceinline__ unsigned long long fma2(unsigned long long a,
                                                   unsigned long long b,
                                                   unsigned long long c) {
    unsigned long long d;
    asm("fma.rn.f32x2 %0, %1, %2, %3;" : "=l"(d) : "l"(a), "l"(b), "l"(c));
    return d;
}

__device__ __forceinline__ void cpasync16(void* smem, const void* gmem) {
    unsigned s = (unsigned)__cvta_generic_to_shared(smem);
    asm volatile("cp.async.cg.shared.global [%0], [%1], 16;\n" :: "r"(s), "l"(gmem));
}
#define CP_COMMIT() asm volatile("cp.async.commit_group;\n" ::: "memory")
#define CP_WAIT1()  asm volatile("cp.async.wait_group 1;\n" ::: "memory")

__device__ __forceinline__ void mma_bf16(float* d, const unsigned* a, const unsigned* b) {
    asm volatile(
        "mma.sync.aligned.m16n8k16.row.col.f32.bf16.bf16.f32 "
        "{%0,%1,%2,%3},{%4,%5,%6,%7},{%8,%9},{%0,%1,%2,%3};\n"
        : "+f"(d[0]), "+f"(d[1]), "+f"(d[2]), "+f"(d[3])
        : "r"(a[0]), "r"(a[1]), "r"(a[2]), "r"(a[3]), "r"(b[0]), "r"(b[1]));
}

// ================= conv + relu + maxpool -> bf16 hi/lo, pixel-major k' =================
// One block per sample; each thread = one pooled pixel across all 32 channels,
// output written as 8x STG.128 (vs 64x STG.16 before).
// Tail blocks: fc-weight fp32 -> bf16 hi/lo with k-permutation (smem transpose).
__global__ void __launch_bounds__(256, 2) conv_pool_kernel(const float* __restrict__ X,
                                                           const float* __restrict__ Wc,
                                                           const float* __restrict__ bc,
                                                           const float* __restrict__ Wfc) {
    extern __shared__ float sh[];
    int tid = threadIdx.x;

    if (blockIdx.x >= NS) {
        // ---- weight transpose tail: one block per (n, 64-pixel chunk) ----
        int bid2 = blockIdx.x - NS;
        int n = bid2 >> 4;
        int chunk = bid2 & 15;
        int pix0 = chunk * 64;
        float (*tile)[65] = (float(*)[65])sh;

        int ch = tid >> 3;               // 0..31
        int pg = tid & 7;                // 8 pixel-groups of 8
#pragma unroll
        for (int i = 0; i < 8; i++) {
            int px = pg * 8 + i;
            int gp = pix0 + px;
            tile[ch][px] = (gp < 961) ? Wfc[(size_t)n * KDIM + ch * 961 + gp] : 0.f;
        }
        __syncthreads();

        unsigned* Whu = (unsigned*)g_Wh;
        unsigned* Wlu = (unsigned*)g_Wl;
#pragma unroll
        for (int j = 0; j < 4; j++) {
            int u = j * 256 + tid;       // 0..1023
            int px = u >> 4;
            int cp = u & 15;             // channel pair
            int gp = pix0 + px;
            if (gp < 961) {
                float v0 = tile[2 * cp][px];
                float v1 = tile[2 * cp + 1][px];
                __nv_bfloat16 h0, l0, h1, l1;
                bf16split(v0, h0, l0);
                bf16split(v1, h1, l1);
                size_t du = (size_t)n * (KDIM / 2) + (size_t)gp * 16 + cp;
                Whu[du] = (unsigned)__bfloat16_as_ushort(h0) |
                          ((unsigned)__bfloat16_as_ushort(h1) << 16);
                Wlu[du] = (unsigned)__bfloat16_as_ushort(l0) |
                          ((unsigned)__bfloat16_as_ushort(l1) << 16);
            }
        }
        return;
    }

    float* sIn = sh;                                              // 12288 floats
    unsigned long long* sWp = (unsigned long long*)(sh + 12288);  // 864 packed (w,w)
    float* sB = (float*)(sWp + 864);                              // 32
    int s = blockIdx.x;

    const float4* xin = (const float4*)(X + (size_t)s * (CIN * HW * HW));
    float4* s4 = (float4*)sIn;
    for (int i = tid; i < 12288 / 4; i += 256) s4[i] = xin[i];
    for (int i = tid; i < 864; i += 256) {
        float w = Wc[i];
        sWp[i] = pk2(w, w);
    }
    if (tid < 32) sB[tid] = bc[tid];
    __syncthreads();

    for (int pixel = tid; pixel < 961; pixel += 256) {
        int ph = pixel / 31;
        int pw = pixel - ph * 31;

        // patch pairs: P[ci][row][j] = packed f32x2 of (col 2j.., col 2j+1..)
        unsigned long long P[3][4][3];
#pragma unroll
        for (int ci = 0; ci < 3; ci++)
#pragma unroll
            for (int r = 0; r < 4; r++) {
                int off = ci * 4096 + (2 * ph + r) * 64 + 2 * pw;  // even -> 8B aligned
                unsigned long long q0 = *(const unsigned long long*)&sIn[off];
                unsigned long long q1 = *(const unsigned long long*)&sIn[off + 2];
                P[ci][r][0] = q0;
                P[ci][r][2] = q1;
                float2 a = upk2(q0), b = upk2(q1);
                P[ci][r][1] = pk2(a.y, b.x);
            }

        size_t outOff = (size_t)s * KDIM + (size_t)pixel * 32;   // k' = pixel*32 + ch
#pragma unroll
        for (int g = 0; g < 4; g++) {
            unsigned hq[4], lq[4];
#pragma unroll
            for (int cc = 0; cc < 8; cc++) {
                int ch = g * 8 + cc;
                const unsigned long long* wp = sWp + ch * 27;
                unsigned long long acc01 = 0ull;   // (a00, a01)
                unsigned long long acc23 = 0ull;   // (a10, a11)
#pragma unroll
                for (int ci = 0; ci < 3; ci++)
#pragma unroll
                    for (int ky = 0; ky < 3; ky++)
#pragma unroll
                        for (int kx = 0; kx < 3; kx++) {
                            unsigned long long w2 = wp[ci * 9 + ky * 3 + kx];
                            acc01 = fma2(w2, P[ci][ky][kx], acc01);
                            acc23 = fma2(w2, P[ci][ky + 1][kx], acc23);
                        }
                float2 v01 = upk2(acc01);
                float2 v23 = upk2(acc23);
                float v = fmaxf(fmaxf(v01.x, v01.y), fmaxf(v23.x, v23.y)) + sB[ch];
                v = fmaxf(v, 0.0f);
                __nv_bfloat16 h, l;
                bf16split(v, h, l);
                if ((cc & 1) == 0) {
                    hq[cc >> 1] = (unsigned)__bfloat16_as_ushort(h);
                    lq[cc >> 1] = (unsigned)__bfloat16_as_ushort(l);
                } else {
                    hq[cc >> 1] |= (unsigned)__bfloat16_as_ushort(h) << 16;
                    lq[cc >> 1] |= (unsigned)__bfloat16_as_ushort(l) << 16;
                }
            }
            *(uint4*)(g_F0h + outOff + g * 8) = make_uint4(hq[0], hq[1], hq[2], hq[3]);
            *(uint4*)(g_F0l + outOff + g * 8) = make_uint4(lq[0], lq[1], lq[2], lq[3]);
        }
    }
}

// ================= FC GEMM: tensor cores, bf16 split-2, split-K=4 =================
#define ST_H  15360
#define OFF_AL 5120
#define OFF_BH 10240
#define OFF_BL 12800

__global__ void __launch_bounds__(256) fc_gemm_tc(void) {
    extern __shared__ __nv_bfloat16 sm[];
    int tid = threadIdx.x;
    int n0 = blockIdx.x * BN;
    int m0 = blockIdx.y * BM;
    int z  = blockIdx.z;

    const int NKT = KDIM / BKT;
    int itStart = (NKT * z) / SPLITK;
    int itEnd   = (NKT * (z + 1)) / SPLITK;
    int nIter   = itEnd - itStart;

    int warp = tid >> 5;
    int wm = warp >> 1;
    int wn = warp & 1;
    int lane = tid & 31;
    int gr = lane >> 2;
    int gc = lane & 3;

    float acc[2][4][4];
#pragma unroll
    for (int mt = 0; mt < 2; mt++)
#pragma unroll
        for (int nt = 0; nt < 4; nt++)
#pragma unroll
            for (int i = 0; i < 4; i++) acc[mt][nt][i] = 0.f;

    int arow0 = (tid >> 2);
    int acc0  = (tid & 3) * 8;
    int brow  = tid >> 2;
    int bcc   = (tid & 3) * 8;

    auto loadStage = [&](int st, int iter) {
        __nv_bfloat16* base = sm + st * ST_H;
        int kt = iter * BKT;
#pragma unroll
        for (int i = 0; i < 2; i++) {
            int row = arow0 + i * 64;
            size_t gsrc = (size_t)(m0 + row) * KDIM + kt + acc0;
            cpasync16(base + row * LDA + acc0, g_F0h + gsrc);
            cpasync16(base + OFF_AL + row * LDA + acc0, g_F0l + gsrc);
        }
        size_t gb = (size_t)(n0 + brow) * KDIM + kt + bcc;
        cpasync16(base + OFF_BH + brow * LDA + bcc, g_Wh + gb);
        cpasync16(base + OFF_BL + brow * LDA + bcc, g_Wl + gb);
    };

#pragma unroll
    for (int s = 0; s < STAGES - 1; s++) {
        if (s < nIter) loadStage(s, itStart + s);
        CP_COMMIT();
    }

    for (int it = 0; it < nIter; it++) {
        CP_WAIT1();
        __syncthreads();
        if (it + STAGES - 1 < nIter) loadStage((it + STAGES - 1) % STAGES, itStart + it + STAGES - 1);
        CP_COMMIT();

        const __nv_bfloat16* base = sm + (it % STAGES) * ST_H;
        const __nv_bfloat16* Ah = base;
        const __nv_bfloat16* Al = base + OFF_AL;
        const __nv_bfloat16* Bh = base + OFF_BH;
        const __nv_bfloat16* Bl = base + OFF_BL;

#pragma unroll
        for (int ks = 0; ks < BKT; ks += 16) {
            unsigned ah[2][4], al[2][4], bh[4][2], bl[4][2];
#pragma unroll
            for (int mt = 0; mt < 2; mt++) {
                int rb = (wm * 32 + mt * 16 + gr) * LDA + ks + gc * 2;
                ah[mt][0] = *(const unsigned*)&Ah[rb];
                ah[mt][1] = *(const unsigned*)&Ah[rb + 8 * LDA];
                ah[mt][2] = *(const unsigned*)&Ah[rb + 8];
                ah[mt][3] = *(const unsigned*)&Ah[rb + 8 * LDA + 8];
                al[mt][0] = *(const unsigned*)&Al[rb];
                al[mt][1] = *(const unsigned*)&Al[rb + 8 * LDA];
                al[mt][2] = *(const unsigned*)&Al[rb + 8];
                al[mt][3] = *(const unsigned*)&Al[rb + 8 * LDA + 8];
            }
#pragma unroll
            for (int nt = 0; nt < 4; nt++) {
                int rb = (wn * 32 + nt * 8 + gr) * LDA + ks + gc * 2;
                bh[nt][0] = *(const unsigned*)&Bh[rb];
                bh[nt][1] = *(const unsigned*)&Bh[rb + 8];
                bl[nt][0] = *(const unsigned*)&Bl[rb];
                bl[nt][1] = *(const unsigned*)&Bl[rb + 8];
            }
#pragma unroll
            for (int mt = 0; mt < 2; mt++)
#pragma unroll
                for (int nt = 0; nt < 4; nt++) {
                    mma_bf16(acc[mt][nt], ah[mt], bh[nt]);
                    mma_bf16(acc[mt][nt], ah[mt], bl[nt]);
                    mma_bf16(acc[mt][nt], al[mt], bh[nt]);
                }
        }
        __syncthreads();
    }

#pragma unroll
    for (int mt = 0; mt < 2; mt++)
#pragma unroll
        for (int nt = 0; nt < 4; nt++) {
            int row = m0 + wm * 32 + mt * 16 + gr;
            int col = n0 + wn * 32 + nt * 8 + gc * 2;
            float* d0 = &g_Cpart[((size_t)z * NS + row) * FF + col];
            d0[0] = acc[mt][nt][0];
            d0[1] = acc[mt][nt][1];
            float* d1 = &g_Cpart[((size_t)z * NS + row + 8) * FF + col];
            d1[0] = acc[mt][nt][2];
            d1[1] = acc[mt][nt][3];
        }
}

__global__ void fc_reduce_kernel(const float* __restrict__ fb) {
    int i = blockIdx.x * 256 + threadIdx.x;
    float v = g_Cpart[i] + g_Cpart[NS * FF + i] + g_Cpart[2 * NS * FF + i]
            + g_Cpart[3 * NS * FF + i] + fb[i & 255];
    g_feats[i] = fmaxf(v, 0.f);
}

// ================= Gram =================
__global__ void gram_kernel() {
    __shared__ float As[32][33];
    __shared__ float Bs[32][33];
    int b  = blockIdx.x;
    int i0 = blockIdx.y * 32;
    int j0 = blockIdx.z * 32;
    const float* f = g_feats + (size_t)b * SS * FF;
    int tid = threadIdx.x;
    int ty = tid >> 4, tx = tid & 15;

    float acc[2][2] = {{0.f, 0.f}, {0.f, 0.f}};
    for (int kc = 0; kc < 256; kc += 32) {
        int row = tid >> 3, kq = tid & 7;
        float4 va = *(const float4*)&f[(i0 + row) * 256 + kc + kq * 4];
        As[row][kq * 4 + 0] = va.x; As[row][kq * 4 + 1] = va.y;
        As[row][kq * 4 + 2] = va.z; As[row][kq * 4 + 3] = va.w;
        float4 vb = *(const float4*)&f[(j0 + row) * 256 + kc + kq * 4];
        Bs[row][kq * 4 + 0] = vb.x; Bs[row][kq * 4 + 1] = vb.y;
        Bs[row][kq * 4 + 2] = vb.z; Bs[row][kq * 4 + 3] = vb.w;
        __syncthreads();
#pragma unroll
        for (int kk = 0; kk < 32; kk++) {
            float a0 = As[ty * 2 + 0][kk];
            float a1 = As[ty * 2 + 1][kk];
            float b0 = Bs[tx * 2 + 0][kk];
            float b1 = Bs[tx * 2 + 1][kk];
            acc[0][0] = fmaf(a0, b0, acc[0][0]);
            acc[0][1] = fmaf(a0, b1, acc[0][1]);
            acc[1][0] = fmaf(a1, b0, acc[1][0]);
            acc[1][1] = fmaf(a1, b1, acc[1][1]);
        }
        __syncthreads();
    }
#pragma unroll
    for (int i = 0; i < 2; i++)
#pragma unroll
        for (int j = 0; j < 2; j++)
            g_G[(size_t)b * SS * SS + (i0 + ty * 2 + i) * SS + (j0 + tx * 2 + j)] = acc[i][j];
}

__global__ void dist_kernel() {
    int idx = blockIdx.x * 256 + threadIdx.x;
    int b = idx / (SS * SS);
    int r = idx - b * SS * SS;
    int i = r / SS, j = r - i * SS;
    const float* G = g_G + (size_t)b * SS * SS;
    float d = G[i * SS + i] + G[j * SS + j] - 2.f * G[i * SS + j];
    g_D[idx] = fmaxf(d, 0.f);
}

// ================= barrier reset =================
__global__ void bar_reset_kernel() {
    g_bar_count = 0;
    g_bar_gen = 0;
}

// software grid barrier: monotonic-count, generation-based; acquire-load poll
__device__ __forceinline__ void grid_bar(unsigned gen, unsigned nb) {
    __syncthreads();
    if (threadIdx.x == 0) {
        __threadfence();   // release: orders stcg(p) before arrival/publish
        unsigned arrived = atomicAdd(&g_bar_count, 1u) + 1u;
        if (arrived == gen * nb) {
            atomicExch(&g_bar_gen, gen);
        } else {
            unsigned g;
            do {
                asm volatile("ld.global.acquire.gpu.u32 %0, [%1];"
                             : "=r"(g) : "l"(&g_bar_gen));
            } while (g < gen);
        }
    }
    __syncthreads();
}

// ================= persistent OT solver: all 60 steps in one kernel =================
__global__ void __launch_bounds__(256, 2) ot_persist(const float* __restrict__ Q,
                                                     const float* __restrict__ theta,
                                                     float* __restrict__ out) {
    __shared__ float Dsh[SS * SS];       // 36864 B
    __shared__ float pk[KK * SS];        // 3840 B
    __shared__ float wsh[SS];
    __shared__ float Qsh[SS];
    __shared__ float psum[8][SS];        // 3072 B
    __shared__ float csum[8];
    __shared__ float s_cost;

    int bk = blockIdx.x;
    int b  = bk / KK;
    int k  = bk - b * KK;
    int tid = threadIdx.x;
    int lane = tid & 31;
    int wid  = tid >> 5;
    unsigned nb = gridDim.x;

    const float4* D4 = (const float4*)(g_D + (size_t)b * SS * SS);
    float4* Ds4 = (float4*)Dsh;
    for (int i = tid; i < (SS * SS) / 4; i += 256) Ds4[i] = D4[i];
    if (tid < SS) Qsh[tid] = Q[bk * SS + tid];
    float th = theta[k];
    __syncthreads();

    float s[12][3];

    // ---- init: s = 1/96, publish p0 and cost0 ----
    {
        const float inv = 1.0f / (float)SS;
        float pacc0 = 0.f, pacc1 = 0.f, pacc2 = 0.f, cacc = 0.f;
#pragma unroll
        for (int ri = 0; ri < 12; ri++) {
            int r = wid + ri * 8;
            float Qi = Qsh[r];
            s[ri][0] = inv; s[ri][1] = inv; s[ri][2] = inv;
            float g = Qi * inv;
            pacc0 += g; pacc1 += g; pacc2 += g;
            cacc += g * (Dsh[r * SS + lane] + Dsh[r * SS + lane + 32] + Dsh[r * SS + lane + 64]);
        }
        psum[wid][lane] = pacc0; psum[wid][lane + 32] = pacc1; psum[wid][lane + 64] = pacc2;
#pragma unroll
        for (int o = 16; o; o >>= 1) cacc += __shfl_xor_sync(0xffffffffu, cacc, o);
        if (lane == 0) csum[wid] = cacc;
        __syncthreads();
        if (tid < SS) {
            float p = 0.f;
#pragma unroll
            for (int w2 = 0; w2 < 8; w2++) p += psum[w2][tid];
            __stcg(&g_pex[0][bk * SS + tid], p);
        }
        if (tid == 0) {
            float c = 0.f;
#pragma unroll
            for (int w2 = 0; w2 < 8; w2++) c += csum[w2];
            s_cost = c;
        }
    }
    unsigned gen = 1;
    grid_bar(gen, nb);

    // ---- 60 solver steps ----
    for (int t = 1; t <= NSTEPS; t++) {
        for (int i = tid; i < KK * SS; i += 256)
            pk[i] = __ldcg(&g_pex[(t - 1) & 1][b * KK * SS + i]);
        __syncthreads();

        if (tid < SS) {
            float m = -1e30f;
#pragma unroll
            for (int kk = 0; kk < KK; kk++) m = fmaxf(m, pk[kk * SS + tid]);
            float zs = 0.f, ek = 0.f;
#pragma unroll
            for (int kk = 0; kk < KK; kk++) {
                float e = __expf((pk[kk * SS + tid] - m) * (1.0f / TAUc));
                zs += e;
                if (kk == k) ek = e;
            }
            wsh[tid] = ek / zs;
        }
        __syncthreads();

        float lam = 2.0f * RHOc * fmaxf(s_cost - th, 0.0f);
        float w0 = wsh[lane], w1 = wsh[lane + 32], w2 = wsh[lane + 64];

        float pacc0 = 0.f, pacc1 = 0.f, pacc2 = 0.f, cacc = 0.f;
#pragma unroll
        for (int ri = 0; ri < 12; ri++) {
            int r = wid + ri * 8;
            float Qi = Qsh[r];
            float d0 = Dsh[r * SS + lane];
            float d1 = Dsh[r * SS + lane + 32];
            float d2 = Dsh[r * SS + lane + 64];
            float G0 = fmaf(lam, d0, w0);
            float G1 = fmaf(lam, d1, w1);
            float G2 = fmaf(lam, d2, w2);
            float s0 = s[ri][0], s1 = s[ri][1], s2 = s[ri][2];

            float dt = s0 * G0 + s1 * G1 + s2 * G2;
#pragma unroll
            for (int o = 16; o; o >>= 1) dt += __shfl_xor_sync(0xffffffffu, dt, o);

            float sc = LRc * Qi;
            float x0 = fminf(fmaxf(sc * s0 * (G0 - dt), -80.f), 80.f);
            float x1 = fminf(fmaxf(sc * s1 * (G1 - dt), -80.f), 80.f);
            float x2 = fminf(fmaxf(sc * s2 * (G2 - dt), -80.f), 80.f);
            float e0 = s0 * __expf(-x0);
            float e1 = s1 * __expf(-x1);
            float e2 = s2 * __expf(-x2);
            float ns = e0 + e1 + e2;
#pragma unroll
            for (int o = 16; o; o >>= 1) ns += __shfl_xor_sync(0xffffffffu, ns, o);
            float rinv = __fdividef(1.0f, ns);
            s0 = e0 * rinv; s1 = e1 * rinv; s2 = e2 * rinv;
            s[ri][0] = s0; s[ri][1] = s1; s[ri][2] = s2;

            pacc0 += Qi * s0; pacc1 += Qi * s1; pacc2 += Qi * s2;
            cacc += Qi * (s0 * d0 + s1 * d1 + s2 * d2);
        }

        psum[wid][lane] = pacc0; psum[wid][lane + 32] = pacc1; psum[wid][lane + 64] = pacc2;
#pragma unroll
        for (int o = 16; o; o >>= 1) cacc += __shfl_xor_sync(0xffffffffu, cacc, o);
        if (lane == 0) csum[wid] = cacc;
        __syncthreads();
        if (tid < SS) {
            float p = 0.f;
#pragma unroll
            for (int w2 = 0; w2 < 8; w2++) p += psum[w2][tid];
            if (t == NSTEPS) out[bk * SS + tid] = p;
            else            __stcg(&g_pex[t & 1][bk * SS + tid], p);
        }
        if (tid == 0) {
            float c = 0.f;
#pragma unroll
            for (int w2 = 0; w2 < 8; w2++) c += csum[w2];
            s_cost = c;
        }
        if (t < NSTEPS) grid_bar(++gen, nb);
    }
}

// ================= launch =================
extern "C" void kernel_launch(void* const* d_in, const int* in_sizes, int n_in,
                              void* d_out, int out_size) {
    const float* X      = (const float*)d_in[0];
    const float* Q      = (const float*)d_in[1];
    const float* conv_w = (const float*)d_in[2];
    const float* conv_b = (const float*)d_in[3];
    const float* fc_w   = (const float*)d_in[4];
    const float* fc_b   = (const float*)d_in[5];
    const float* theta  = (const float*)d_in[6];
    float* out = (float*)d_out;

    const int CONV_SMEM = 12288 * 4 + 864 * 8 + 32 * 4;   // 56192 B (>= transpose tile 8320 B)
    cudaFuncSetAttribute(conv_pool_kernel, cudaFuncAttributeMaxDynamicSharedMemorySize, CONV_SMEM);
    cudaFuncSetAttribute(fc_gemm_tc, cudaFuncAttributeMaxDynamicSharedMemorySize, STAGES * ST_H * 2);
    cudaFuncSetAttribute(ot_persist, cudaFuncAttributePreferredSharedMemoryCarveout, 100);

    conv_pool_kernel<<<NS + WT_BLOCKS, 256, CONV_SMEM>>>(X, conv_w, conv_b, fc_w);

    dim3 gg(FF / BN, NS / BM, SPLITK);   // 4 x 12 x 4 = 192 blocks
    fc_gemm_tc<<<gg, 256, STAGES * ST_H * 2>>>();
    fc_reduce_kernel<<<(NS * FF) / 256, 256>>>(fc_b);

    gram_kernel<<<dim3(16, 3, 3), 256>>>();
    dist_kernel<<<(BB * SS * SS) / 256, 256>>>();

    bar_reset_kernel<<<1, 1>>>();
    ot_persist<<<BB * KK, 256>>>(Q, theta, out);
}

// round 17
// speedup vs baseline: 3.3701x; 3.3701x over previous
#include <cuda_runtime.h>
#include <cuda_bf16.h>
#include <cstddef>

// ---------------- problem dims ----------------
#define BB 16
#define SS 96
#define KK 10
#define FF 256
#define NS 1536            // BB*SS samples
#define CIN 3
#define HW 64
#define FEATC 30752        // 32*31*31
#define KDIM 30752

#define TAUc 0.05f
#define RHOc 10.0f
#define LRc 0.5f
#define NSTEPS 60

// GEMM tiling
#define BM 128
#define BN 64
#define BKT 32
#define STAGES 3
#define LDA 40              // halves per smem row (stride-40 => conflict-free 4B LDS)
#define SPLITK 3            // 4x12x3 = 144 blocks -> single wave on 148 SMs

// ---------------- scratch (__device__ globals; no allocations) ----------------
__device__ __nv_bfloat16 g_F0h[(size_t)NS * KDIM];   // conv features hi (k = ch*961 + pixel)
__device__ __nv_bfloat16 g_F0l[(size_t)NS * KDIM];   // conv features lo
__device__ __nv_bfloat16 g_Wh[(size_t)FF * KDIM];    // fc weights hi
__device__ __nv_bfloat16 g_Wl[(size_t)FF * KDIM];    // fc weights lo
__device__ float g_Cpart[SPLITK * NS * FF];          // split-K partials
__device__ float g_feats[NS * FF];                   // fc output features
__device__ float g_G[BB * SS * SS];                  // Gram
__device__ float g_D[BB * SS * SS];                  // pairwise sq distances
__device__ float g_pex[2][BB * KK * SS];             // ping-pong p exchange
__device__ unsigned g_bar_count[BB * 32];            // per-batch barrier counters (128B padded)
__device__ unsigned g_bar_gen[BB * 32];

// ---------------- helpers ----------------
__device__ __forceinline__ void bf16split(float v, __nv_bfloat16& h, __nv_bfloat16& l) {
    h = __float2bfloat16(v);
    l = __float2bfloat16(v - __bfloat162float(h));
}

__device__ __forceinline__ unsigned long long pk2(float lo, float hi) {
    unsigned long long r;
    asm("mov.b64 %0, {%1,%2};" : "=l"(r) : "f"(lo), "f"(hi));
    return r;
}
__device__ __forceinline__ float2 upk2(unsigned long long v) {
    float2 f;
    asm("mov.b64 {%0,%1}, %2;" : "=f"(f.x), "=f"(f.y) : "l"(v));
    return f;
}
__device__ __forceinline__ unsigned long long fma2(unsigned long long a,
                                                   unsigned long long b,
                                                   unsigned long long c) {
    unsigned long long d;
    asm("fma.rn.f32x2 %0, %1, %2, %3;" : "=l"(d) : "l"(a), "l"(b), "l"(c));
    return d;
}

__device__ __forceinline__ void cpasync16(void* smem, const void* gmem) {
    unsigned s = (unsigned)__cvta_generic_to_shared(smem);
    asm volatile("cp.async.cg.shared.global [%0], [%1], 16;\n" :: "r"(s), "l"(gmem));
}
#define CP_COMMIT() asm volatile("cp.async.commit_group;\n" ::: "memory")
#define CP_WAIT1()  asm volatile("cp.async.wait_group 1;\n" ::: "memory")

__device__ __forceinline__ void mma_bf16(float* d, const unsigned* a, const unsigned* b) {
    asm volatile(
        "mma.sync.aligned.m16n8k16.row.col.f32.bf16.bf16.f32 "
        "{%0,%1,%2,%3},{%4,%5,%6,%7},{%8,%9},{%0,%1,%2,%3};\n"
        : "+f"(d[0]), "+f"(d[1]), "+f"(d[2]), "+f"(d[3])
        : "r"(a[0]), "r"(a[1]), "r"(a[2]), "r"(a[3]), "r"(b[0]), "r"(b[1]));
}

// ================= conv + relu + maxpool -> bf16 hi/lo (f32x2 packed FMA) =================
// One block per sample; each thread computes whole pooled pixels across all 32 channels.
// Channel-major k (= ch*961 + pixel): warp STG.16 writes 64 contiguous bytes.
__global__ void __launch_bounds__(256, 2) conv_pool_kernel(const float* __restrict__ X,
                                                           const float* __restrict__ Wc,
                                                           const float* __restrict__ bc,
                                                           const float* __restrict__ Wfc) {
    // tail blocks: fc-weight fp32 -> bf16 hi/lo conversion (overlaps with conv)
    if (blockIdx.x >= NS) {
        int bid2 = blockIdx.x - NS;
        const float4* W4 = (const float4*)Wfc;
        for (size_t i = (size_t)bid2 * 256 + threadIdx.x; i < (size_t)(FF * KDIM) / 4; i += 128 * 256) {
            float4 v = W4[i];
            __nv_bfloat16 h0, l0, h1, l1, h2, l2, h3, l3;
            bf16split(v.x, h0, l0); bf16split(v.y, h1, l1);
            bf16split(v.z, h2, l2); bf16split(v.w, h3, l3);
            *(ushort4*)(g_Wh + i * 4) = make_ushort4(__bfloat16_as_ushort(h0), __bfloat16_as_ushort(h1),
                                                     __bfloat16_as_ushort(h2), __bfloat16_as_ushort(h3));
            *(ushort4*)(g_Wl + i * 4) = make_ushort4(__bfloat16_as_ushort(l0), __bfloat16_as_ushort(l1),
                                                     __bfloat16_as_ushort(l2), __bfloat16_as_ushort(l3));
        }
        return;
    }

    extern __shared__ float sh[];
    float* sIn = sh;                                              // 12288 floats
    unsigned long long* sWp = (unsigned long long*)(sh + 12288);  // 864 packed (w,w)
    float* sB = (float*)(sWp + 864);                              // 32
    int s = blockIdx.x;
    int tid = threadIdx.x;

    const float4* xin = (const float4*)(X + (size_t)s * (CIN * HW * HW));
    float4* s4 = (float4*)sIn;
    for (int i = tid; i < 12288 / 4; i += 256) s4[i] = xin[i];
    for (int i = tid; i < 864; i += 256) {
        float w = Wc[i];
        sWp[i] = pk2(w, w);
    }
    if (tid < 32) sB[tid] = bc[tid];
    __syncthreads();

    for (int pixel = tid; pixel < 961; pixel += 256) {
        int ph = pixel / 31;
        int pw = pixel - ph * 31;

        // patch pairs: P[ci][row][j] = packed f32x2
        unsigned long long P[3][4][3];
#pragma unroll
        for (int ci = 0; ci < 3; ci++)
#pragma unroll
            for (int r = 0; r < 4; r++) {
                int off = ci * 4096 + (2 * ph + r) * 64 + 2 * pw;  // even -> 8B aligned
                unsigned long long q0 = *(const unsigned long long*)&sIn[off];
                unsigned long long q1 = *(const unsigned long long*)&sIn[off + 2];
                P[ci][r][0] = q0;
                P[ci][r][2] = q1;
                float2 a = upk2(q0), b = upk2(q1);
                P[ci][r][1] = pk2(a.y, b.x);
            }

        size_t outb = (size_t)s * KDIM + pixel;
#pragma unroll 2
        for (int ch = 0; ch < 32; ch++) {
            const unsigned long long* wp = sWp + ch * 27;
            unsigned long long acc01 = 0ull;   // (a00, a01)
            unsigned long long acc23 = 0ull;   // (a10, a11)
#pragma unroll
            for (int ci = 0; ci < 3; ci++)
#pragma unroll
                for (int ky = 0; ky < 3; ky++)
#pragma unroll
                    for (int kx = 0; kx < 3; kx++) {
                        unsigned long long w2 = wp[ci * 9 + ky * 3 + kx];
                        acc01 = fma2(w2, P[ci][ky][kx], acc01);
                        acc23 = fma2(w2, P[ci][ky + 1][kx], acc23);
                    }
            float2 v01 = upk2(acc01);
            float2 v23 = upk2(acc23);
            float v = fmaxf(fmaxf(v01.x, v01.y), fmaxf(v23.x, v23.y)) + sB[ch];
            v = fmaxf(v, 0.0f);
            __nv_bfloat16 h, l;
            bf16split(v, h, l);
            g_F0h[outb + ch * 961] = h;
            g_F0l[outb + ch * 961] = l;
        }
    }
}

// ================= FC GEMM: tensor cores, bf16 split-2, split-K=3 =================
#define ST_H  15360
#define OFF_AL 5120
#define OFF_BH 10240
#define OFF_BL 12800

__global__ void __launch_bounds__(256) fc_gemm_tc(void) {
    extern __shared__ __nv_bfloat16 sm[];
    int tid = threadIdx.x;
    int n0 = blockIdx.x * BN;
    int m0 = blockIdx.y * BM;
    int z  = blockIdx.z;

    const int NKT = KDIM / BKT;                 // 961
    int itStart = (NKT * z) / SPLITK;
    int itEnd   = (NKT * (z + 1)) / SPLITK;
    int nIter   = itEnd - itStart;

    int warp = tid >> 5;
    int wm = warp >> 1;
    int wn = warp & 1;
    int lane = tid & 31;
    int gr = lane >> 2;
    int gc = lane & 3;

    float acc[2][4][4];
#pragma unroll
    for (int mt = 0; mt < 2; mt++)
#pragma unroll
        for (int nt = 0; nt < 4; nt++)
#pragma unroll
            for (int i = 0; i < 4; i++) acc[mt][nt][i] = 0.f;

    int arow0 = (tid >> 2);
    int acc0  = (tid & 3) * 8;
    int brow  = tid >> 2;
    int bcc   = (tid & 3) * 8;

    auto loadStage = [&](int st, int iter) {
        __nv_bfloat16* base = sm + st * ST_H;
        int kt = iter * BKT;
#pragma unroll
        for (int i = 0; i < 2; i++) {
            int row = arow0 + i * 64;
            size_t gsrc = (size_t)(m0 + row) * KDIM + kt + acc0;
            cpasync16(base + row * LDA + acc0, g_F0h + gsrc);
            cpasync16(base + OFF_AL + row * LDA + acc0, g_F0l + gsrc);
        }
        size_t gb = (size_t)(n0 + brow) * KDIM + kt + bcc;
        cpasync16(base + OFF_BH + brow * LDA + bcc, g_Wh + gb);
        cpasync16(base + OFF_BL + brow * LDA + bcc, g_Wl + gb);
    };

#pragma unroll
    for (int s = 0; s < STAGES - 1; s++) {
        if (s < nIter) loadStage(s, itStart + s);
        CP_COMMIT();
    }

    for (int it = 0; it < nIter; it++) {
        CP_WAIT1();
        __syncthreads();
        if (it + STAGES - 1 < nIter) loadStage((it + STAGES - 1) % STAGES, itStart + it + STAGES - 1);
        CP_COMMIT();

        const __nv_bfloat16* base = sm + (it % STAGES) * ST_H;
        const __nv_bfloat16* Ah = base;
        const __nv_bfloat16* Al = base + OFF_AL;
        const __nv_bfloat16* Bh = base + OFF_BH;
        const __nv_bfloat16* Bl = base + OFF_BL;

#pragma unroll
        for (int ks = 0; ks < BKT; ks += 16) {
            unsigned ah[2][4], al[2][4], bh[4][2], bl[4][2];
#pragma unroll
            for (int mt = 0; mt < 2; mt++) {
                int rb = (wm * 32 + mt * 16 + gr) * LDA + ks + gc * 2;
                ah[mt][0] = *(const unsigned*)&Ah[rb];
                ah[mt][1] = *(const unsigned*)&Ah[rb + 8 * LDA];
                ah[mt][2] = *(const unsigned*)&Ah[rb + 8];
                ah[mt][3] = *(const unsigned*)&Ah[rb + 8 * LDA + 8];
                al[mt][0] = *(const unsigned*)&Al[rb];
                al[mt][1] = *(const unsigned*)&Al[rb + 8 * LDA];
                al[mt][2] = *(const unsigned*)&Al[rb + 8];
                al[mt][3] = *(const unsigned*)&Al[rb + 8 * LDA + 8];
            }
#pragma unroll
            for (int nt = 0; nt < 4; nt++) {
                int rb = (wn * 32 + nt * 8 + gr) * LDA + ks + gc * 2;
                bh[nt][0] = *(const unsigned*)&Bh[rb];
                bh[nt][1] = *(const unsigned*)&Bh[rb + 8];
                bl[nt][0] = *(const unsigned*)&Bl[rb];
                bl[nt][1] = *(const unsigned*)&Bl[rb + 8];
            }
#pragma unroll
            for (int mt = 0; mt < 2; mt++)
#pragma unroll
                for (int nt = 0; nt < 4; nt++) {
                    mma_bf16(acc[mt][nt], ah[mt], bh[nt]);
                    mma_bf16(acc[mt][nt], ah[mt], bl[nt]);
                    mma_bf16(acc[mt][nt], al[mt], bh[nt]);
                }
        }
        __syncthreads();
    }

#pragma unroll
    for (int mt = 0; mt < 2; mt++)
#pragma unroll
        for (int nt = 0; nt < 4; nt++) {
            int row = m0 + wm * 32 + mt * 16 + gr;
            int col = n0 + wn * 32 + nt * 8 + gc * 2;
            float* d0 = &g_Cpart[((size_t)z * NS + row) * FF + col];
            d0[0] = acc[mt][nt][0];
            d0[1] = acc[mt][nt][1];
            float* d1 = &g_Cpart[((size_t)z * NS + row + 8) * FF + col];
            d1[0] = acc[mt][nt][2];
            d1[1] = acc[mt][nt][3];
        }
}

__global__ void fc_reduce_kernel(const float* __restrict__ fb) {
    int i = blockIdx.x * 256 + threadIdx.x;
    float v = g_Cpart[i] + g_Cpart[NS * FF + i] + g_Cpart[2 * NS * FF + i] + fb[i & 255];
    g_feats[i] = fmaxf(v, 0.f);
}

// ================= Gram =================
__global__ void gram_kernel() {
    __shared__ float As[32][33];
    __shared__ float Bs[32][33];
    int b  = blockIdx.x;
    int i0 = blockIdx.y * 32;
    int j0 = blockIdx.z * 32;
    const float* f = g_feats + (size_t)b * SS * FF;
    int tid = threadIdx.x;
    int ty = tid >> 4, tx = tid & 15;

    float acc[2][2] = {{0.f, 0.f}, {0.f, 0.f}};
    for (int kc = 0; kc < 256; kc += 32) {
        int row = tid >> 3, kq = tid & 7;
        float4 va = *(const float4*)&f[(i0 + row) * 256 + kc + kq * 4];
        As[row][kq * 4 + 0] = va.x; As[row][kq * 4 + 1] = va.y;
        As[row][kq * 4 + 2] = va.z; As[row][kq * 4 + 3] = va.w;
        float4 vb = *(const float4*)&f[(j0 + row) * 256 + kc + kq * 4];
        Bs[row][kq * 4 + 0] = vb.x; Bs[row][kq * 4 + 1] = vb.y;
        Bs[row][kq * 4 + 2] = vb.z; Bs[row][kq * 4 + 3] = vb.w;
        __syncthreads();
#pragma unroll
        for (int kk = 0; kk < 32; kk++) {
            float a0 = As[ty * 2 + 0][kk];
            float a1 = As[ty * 2 + 1][kk];
            float b0 = Bs[tx * 2 + 0][kk];
            float b1 = Bs[tx * 2 + 1][kk];
            acc[0][0] = fmaf(a0, b0, acc[0][0]);
            acc[0][1] = fmaf(a0, b1, acc[0][1]);
            acc[1][0] = fmaf(a1, b0, acc[1][0]);
            acc[1][1] = fmaf(a1, b1, acc[1][1]);
        }
        __syncthreads();
    }
#pragma unroll
    for (int i = 0; i < 2; i++)
#pragma unroll
        for (int j = 0; j < 2; j++)
            g_G[(size_t)b * SS * SS + (i0 + ty * 2 + i) * SS + (j0 + tx * 2 + j)] = acc[i][j];
}

__global__ void dist_kernel() {
    int idx = blockIdx.x * 256 + threadIdx.x;
    int b = idx / (SS * SS);
    int r = idx - b * SS * SS;
    int i = r / SS, j = r - i * SS;
    const float* G = g_G + (size_t)b * SS * SS;
    float d = G[i * SS + i] + G[j * SS + j] - 2.f * G[i * SS + j];
    g_D[idx] = fmaxf(d, 0.f);
}

// ================= barrier reset =================
__global__ void bar_reset_kernel() {
    int i = threadIdx.x;
    if (i < BB) {
        g_bar_count[i * 32] = 0;
        g_bar_gen[i * 32] = 0;
    }
}

// per-batch barrier: only the KK blocks of one batch synchronize (monotonic gen)
__device__ __forceinline__ void batch_bar(int b, unsigned gen) {
    __syncthreads();
    if (threadIdx.x == 0) {
        __threadfence();   // release: orders stcg(p) before arrival/publish
        unsigned arrived = atomicAdd(&g_bar_count[b * 32], 1u) + 1u;
        if (arrived == gen * KK) {
            atomicExch(&g_bar_gen[b * 32], gen);
        } else {
            unsigned g;
            do {
                asm volatile("ld.global.acquire.gpu.u32 %0, [%1];"
                             : "=r"(g) : "l"(&g_bar_gen[b * 32]));
            } while (g < gen);
        }
    }
    __syncthreads();
}

// ================= persistent OT solver: all 60 steps in one kernel =================
__global__ void __launch_bounds__(256, 2) ot_persist(const float* __restrict__ Q,
                                                     const float* __restrict__ theta,
                                                     float* __restrict__ out) {
    __shared__ float Dsh[SS * SS];       // 36864 B
    __shared__ float pk[KK * SS];        // 3840 B
    __shared__ float wsh[SS];
    __shared__ float Qsh[SS];
    __shared__ float psum[8][SS];        // 3072 B
    __shared__ float csum[8];
    __shared__ float s_cost;

    int bk = blockIdx.x;
    int b  = bk / KK;
    int k  = bk - b * KK;
    int tid = threadIdx.x;
    int lane = tid & 31;
    int wid  = tid >> 5;

    const float4* D4 = (const float4*)(g_D + (size_t)b * SS * SS);
    float4* Ds4 = (float4*)Dsh;
    for (int i = tid; i < (SS * SS) / 4; i += 256) Ds4[i] = D4[i];
    if (tid < SS) Qsh[tid] = Q[bk * SS + tid];
    float th = theta[k];
    __syncthreads();

    float s[12][3];

    // ---- init: s = 1/96, publish p0 and cost0 ----
    {
        const float inv = 1.0f / (float)SS;
        float pacc0 = 0.f, pacc1 = 0.f, pacc2 = 0.f, cacc = 0.f;
#pragma unroll
        for (int ri = 0; ri < 12; ri++) {
            int r = wid + ri * 8;
            float Qi = Qsh[r];
            s[ri][0] = inv; s[ri][1] = inv; s[ri][2] = inv;
            float g = Qi * inv;
            pacc0 += g; pacc1 += g; pacc2 += g;
            cacc += g * (Dsh[r * SS + lane] + Dsh[r * SS + lane + 32] + Dsh[r * SS + lane + 64]);
        }
        psum[wid][lane] = pacc0; psum[wid][lane + 32] = pacc1; psum[wid][lane + 64] = pacc2;
#pragma unroll
        for (int o = 16; o; o >>= 1) cacc += __shfl_xor_sync(0xffffffffu, cacc, o);
        if (lane == 0) csum[wid] = cacc;
        __syncthreads();
        if (tid < SS) {
            float p = 0.f;
#pragma unroll
            for (int w2 = 0; w2 < 8; w2++) p += psum[w2][tid];
            __stcg(&g_pex[0][bk * SS + tid], p);
        }
        if (tid == 0) {
            float c = 0.f;
#pragma unroll
            for (int w2 = 0; w2 < 8; w2++) c += csum[w2];
            s_cost = c;
        }
    }
    unsigned gen = 1;
    batch_bar(b, gen);

    // ---- 60 solver steps ----
    for (int t = 1; t <= NSTEPS; t++) {
        for (int i = tid; i < KK * SS; i += 256)
            pk[i] = __ldcg(&g_pex[(t - 1) & 1][b * KK * SS + i]);
        __syncthreads();

        if (tid < SS) {
            float m = -1e30f;
#pragma unroll
            for (int kk = 0; kk < KK; kk++) m = fmaxf(m, pk[kk * SS + tid]);
            float zs = 0.f, ek = 0.f;
#pragma unroll
            for (int kk = 0; kk < KK; kk++) {
                float e = __expf((pk[kk * SS + tid] - m) * (1.0f / TAUc));
                zs += e;
                if (kk == k) ek = e;
            }
            wsh[tid] = ek / zs;
        }
        __syncthreads();

        float lam = 2.0f * RHOc * fmaxf(s_cost - th, 0.0f);
        float w0 = wsh[lane], w1 = wsh[lane + 32], w2 = wsh[lane + 64];

        float pacc0 = 0.f, pacc1 = 0.f, pacc2 = 0.f, cacc = 0.f;
#pragma unroll
        for (int ri = 0; ri < 12; ri++) {
            int r = wid + ri * 8;
            float Qi = Qsh[r];
            float d0 = Dsh[r * SS + lane];
            float d1 = Dsh[r * SS + lane + 32];
            float d2 = Dsh[r * SS + lane + 64];
            float G0 = fmaf(lam, d0, w0);
            float G1 = fmaf(lam, d1, w1);
            float G2 = fmaf(lam, d2, w2);
            float s0 = s[ri][0], s1 = s[ri][1], s2 = s[ri][2];

            float dt = s0 * G0 + s1 * G1 + s2 * G2;
#pragma unroll
            for (int o = 16; o; o >>= 1) dt += __shfl_xor_sync(0xffffffffu, dt, o);

            float sc = LRc * Qi;
            float x0 = fminf(fmaxf(sc * s0 * (G0 - dt), -80.f), 80.f);
            float x1 = fminf(fmaxf(sc * s1 * (G1 - dt), -80.f), 80.f);
            float x2 = fminf(fmaxf(sc * s2 * (G2 - dt), -80.f), 80.f);
            float e0 = s0 * __expf(-x0);
            float e1 = s1 * __expf(-x1);
            float e2 = s2 * __expf(-x2);
            float ns = e0 + e1 + e2;
#pragma unroll
            for (int o = 16; o; o >>= 1) ns += __shfl_xor_sync(0xffffffffu, ns, o);
            float rinv = __fdividef(1.0f, ns);
            s0 = e0 * rinv; s1 = e1 * rinv; s2 = e2 * rinv;
            s[ri][0] = s0; s[ri][1] = s1; s[ri][2] = s2;

            pacc0 += Qi * s0; pacc1 += Qi * s1; pacc2 += Qi * s2;
            cacc += Qi * (s0 * d0 + s1 * d1 + s2 * d2);
        }

        psum[wid][lane] = pacc0; psum[wid][lane + 32] = pacc1; psum[wid][lane + 64] = pacc2;
#pragma unroll
        for (int o = 16; o; o >>= 1) cacc += __shfl_xor_sync(0xffffffffu, cacc, o);
        if (lane == 0) csum[wid] = cacc;
        __syncthreads();
        if (tid < SS) {
            float p = 0.f;
#pragma unroll
            for (int w2 = 0; w2 < 8; w2++) p += psum[w2][tid];
            if (t == NSTEPS) out[bk * SS + tid] = p;
            else            __stcg(&g_pex[t & 1][bk * SS + tid], p);
        }
        if (tid == 0) {
            float c = 0.f;
#pragma unroll
            for (int w2 = 0; w2 < 8; w2++) c += csum[w2];
            s_cost = c;
        }
        if (t < NSTEPS) batch_bar(b, ++gen);
    }
}

// ================= launch =================
extern "C" void kernel_launch(void* const* d_in, const int* in_sizes, int n_in,
                              void* d_out, int out_size) {
    const float* X      = (const float*)d_in[0];
    const float* Q      = (const float*)d_in[1];
    const float* conv_w = (const float*)d_in[2];
    const float* conv_b = (const float*)d_in[3];
    const float* fc_w   = (const float*)d_in[4];
    const float* fc_b   = (const float*)d_in[5];
    const float* theta  = (const float*)d_in[6];
    float* out = (float*)d_out;

    const int CONV_SMEM = 12288 * 4 + 864 * 8 + 32 * 4;   // 56192 B
    cudaFuncSetAttribute(conv_pool_kernel, cudaFuncAttributeMaxDynamicSharedMemorySize, CONV_SMEM);
    cudaFuncSetAttribute(fc_gemm_tc, cudaFuncAttributeMaxDynamicSharedMemorySize, STAGES * ST_H * 2);
    cudaFuncSetAttribute(ot_persist, cudaFuncAttributePreferredSharedMemoryCarveout, 100);

    conv_pool_kernel<<<NS + 128, 256, CONV_SMEM>>>(X, conv_w, conv_b, fc_w);

    dim3 gg(FF / BN, NS / BM, SPLITK);   // 4 x 12 x 3 = 144 blocks (single wave)
    fc_gemm_tc<<<gg, 256, STAGES * ST_H * 2>>>();
    fc_reduce_kernel<<<(NS * FF) / 256, 256>>>(fc_b);

    gram_kernel<<<dim3(16, 3, 3), 256>>>();
    dist_kernel<<<(BB * SS * SS) / 256, 256>>>();

    bar_reset_kernel<<<1, 32>>>();
    ot_persist<<<BB * KK, 256>>>(Q, theta, out);
}